// round 7
// baseline (speedup 1.0000x reference)
#include <cuda_runtime.h>
#include <cuda_fp16.h>

#define TT    512
#define BB    1024
#define OBSN  64
#define HH    256
#define AA    16
#define BM    8
#define NCTA  128
#define NTH   512
#define KTOT  320          // 64 obs rows + 256 h rows
#define SQP   12           // state row stride (floats)
#define WO16P 264          // padded halfs per W_out row (bank-conflict-free)

// persistent transposed weights (allocation-free scratch)
__device__ __half g_W16[KTOT * HH];     // rows [0,64)=W_in^T, [64,320)=W_h^T  ([k][j])
__device__ __half g_Wo16[AA * WO16P];   // W_out fp16, padded rows

__global__ void prep_kernel(const float* __restrict__ W_in,
                            const float* __restrict__ W_h,
                            const float* __restrict__ W_out) {
    int idx = blockIdx.x * blockDim.x + threadIdx.x;
    if (idx < KTOT * HH) {
        int k = idx / HH, j = idx % HH;
        float v = (k < OBSN) ? W_in[j * OBSN + k] : W_h[j * HH + (k - OBSN)];
        g_W16[idx] = __float2half_rn(v);
    }
    if (idx < AA * HH) {
        int a = idx / HH, j = idx % HH;
        g_Wo16[a * WO16P + j] = __float2half_rn(W_out[idx]);
    }
}

typedef unsigned long long u64;

__device__ __forceinline__ u64 pack2(float lo, float hi) {
    u64 u; asm("mov.b64 %0,{%1,%2};" : "=l"(u) : "f"(lo), "f"(hi)); return u;
}
__device__ __forceinline__ void unpack2(u64 v, float& lo, float& hi) {
    asm("mov.b64 {%0,%1},%2;" : "=f"(lo), "=f"(hi) : "l"(v));
}
__device__ __forceinline__ void fma2(u64& d, u64 a, u64 b) {   // packed f32x2 FMA
    asm("fma.rn.f32x2 %0,%1,%2,%0;" : "+l"(d) : "l"(a), "l"(b));
}
__device__ __forceinline__ void add2(u64& d, u64 a) {          // packed f32x2 add
    asm("add.rn.f32x2 %0,%0,%1;" : "+l"(d) : "l"(a));
}
__device__ __forceinline__ float sigf(float x) {
    return __fdividef(1.0f, 1.0f + __expf(-x));
}

// one k-step: acc_r(j0), acc_r(j1) += state[k][r] * w[k][j]
__device__ __forceinline__ void kstep(const float2 w, const float* st,
                                      u64 acc0[4], u64 acc1[4]) {
    u64 w0 = pack2(w.x, w.x), w1 = pack2(w.y, w.y);
    ulonglong2 q0 = *(const ulonglong2*)(st);      // rows 0-3
    ulonglong2 q1 = *(const ulonglong2*)(st + 4);  // rows 4-7
    fma2(acc0[0], q0.x, w0); fma2(acc0[1], q0.y, w0);
    fma2(acc0[2], q1.x, w0); fma2(acc0[3], q1.y, w0);
    fma2(acc1[0], q0.x, w1); fma2(acc1[1], q0.y, w1);
    fma2(acc1[2], q1.x, w1); fma2(acc1[3], q1.y, w1);
}

__global__ void __launch_bounds__(NTH, 1) rnn_kernel(
    const float* __restrict__ obs,
    const float* __restrict__ b_h,
    const float* __restrict__ b_out,
    float* __restrict__ out)
{
    extern __shared__ char smraw[];
    float*  s_state = (float*)smraw;                          // [KTOT][SQP]  15360 B
    float*  s_part  = s_state + KTOT * SQP;                   // 4 areas*3 slots*128*4f  24576 B
    float*  s_hpk   = s_part + 4 * 3 * 128 * 4;               // [4][128][4]   8192 B
    __half* s_hT16  = (__half*)(s_hpk + 4 * 128 * 4);         // [8][HH]       4096 B
    __half* s_Wo16  = s_hT16 + 8 * HH;                        // [AA][WO16P]   8448 B
    __half* s_W16   = s_Wo16 + AA * WO16P;                    // [KTOT][HH]  163840 B

    const int tid   = threadIdx.x;
    const int slice = tid >> 7;          // 0..3 (uniform per warp)
    const int jp    = tid & 127;
    const int j0    = jp * 2;
    const int b0    = blockIdx.x * BM;

    // k-ranges: slice0 smaller so its head work overlaps others' k-loops
    const int kb = (slice == 0) ? 0 : 56 + (slice - 1) * 88;
    const int kc = (slice == 0) ? 56 : 88;

    // ---- one-time init ----
    for (int i = tid; i < KTOT * HH / 8; i += NTH)
        ((uint4*)s_W16)[i] = ((const uint4*)g_W16)[i];
    for (int i = tid; i < AA * WO16P / 2; i += NTH)
        ((uint*)s_Wo16)[i] = ((const uint*)g_Wo16)[i];
    for (int i = tid; i < HH * SQP; i += NTH) s_state[OBSN * SQP + i] = 0.0f;
    for (int i = tid; i < 4 * 128 * 4; i += NTH) s_hpk[i] = 0.0f;

    const float bh0 = b_h[j0], bh1 = b_h[j0 + 1];
    const int r_o = tid >> 4, a_o = tid & 15;      // head mapping (tid<128)
    float bo = (tid < 128) ? b_out[a_o] : 0.0f;
    float o_reg = 0.0f;

    const int ko = jp & 63, rq = jp >> 6;          // obs staging map (slice1)
    if (slice == 1) {                              // stage obs for t=0
        float4 p0;
        p0.x = obs[((b0 + rq * 4 + 0) * TT + 0) * OBSN + ko];
        p0.y = obs[((b0 + rq * 4 + 1) * TT + 0) * OBSN + ko];
        p0.z = obs[((b0 + rq * 4 + 2) * TT + 0) * OBSN + ko];
        p0.w = obs[((b0 + rq * 4 + 3) * TT + 0) * OBSN + ko];
        *(float4*)(s_state + ko * SQP + rq * 4) = p0;
    }
    __syncthreads();

    for (int t = 0; t < TT; ++t) {
        u64 acc0[4] = {0, 0, 0, 0}, acc1[4] = {0, 0, 0, 0};

        float4 pf;
        if (slice == 1) {                          // prefetch obs t+1
            int tn = (t + 1 < TT) ? t + 1 : t;
            pf.x = obs[((b0 + rq * 4 + 0) * TT + tn) * OBSN + ko];
            pf.y = obs[((b0 + rq * 4 + 1) * TT + tn) * OBSN + ko];
            pf.z = obs[((b0 + rq * 4 + 2) * TT + tn) * OBSN + ko];
            pf.w = obs[((b0 + rq * 4 + 3) * TT + tn) * OBSN + ko];
        }

        // ---- k-slice GEMM ----
        const __half2* wrow = (const __half2*)s_W16 + kb * (HH / 2) + jp;
        const float*   st   = s_state + kb * SQP;
        #pragma unroll 8
        for (int k = 0; k < kc; ++k) {
            kstep(__half22float2(*wrow), st, acc0, acc1);
            wrow += HH / 2; st += SQP;
        }

        // ---- publish partials for the 3 other slices (conflict-free STS.128) ----
        #pragma unroll
        for (int rp = 0; rp < 4; ++rp) {
            if (rp != slice) {
                int slot = (slice < rp) ? slice : slice - 1;
                *(ulonglong2*)(s_part + rp * 1536 + (slot * 128 + jp) * 4)
                    = make_ulonglong2(acc0[rp], acc1[rp]);
            }
        }
        __syncthreads();                           // sync_b

        // ---- distributed combine + sigmoid + blend (every thread: 4 elems) ----
        u64 A0, A1;                                // own contribution (constant index)
        if      (slice == 0) { A0 = acc0[0]; A1 = acc1[0]; }
        else if (slice == 1) { A0 = acc0[1]; A1 = acc1[1]; }
        else if (slice == 2) { A0 = acc0[2]; A1 = acc1[2]; }
        else                 { A0 = acc0[3]; A1 = acc1[3]; }
        #pragma unroll
        for (int s = 0; s < 4; ++s) {
            if (s != slice) {
                int slot = (s < slice) ? s : s - 1;
                ulonglong2 v = *(const ulonglong2*)
                    (s_part + slice * 1536 + (slot * 128 + jp) * 4);
                add2(A0, v.x); add2(A1, v.y);
            }
        }
        float q0, q1, q2, q3;
        unpack2(A0, q0, q1); unpack2(A1, q2, q3);

        float4 hold = *(float4*)(s_hpk + (slice * 128 + jp) * 4);
        float h_a = 0.9f * hold.x + 0.1f * sigf(q0 + bh0);   // (j0, r=2s)
        float h_b = 0.9f * hold.y + 0.1f * sigf(q1 + bh0);   // (j0, r=2s+1)
        float h_c = 0.9f * hold.z + 0.1f * sigf(q2 + bh1);   // (j1, r=2s)
        float h_d = 0.9f * hold.w + 0.1f * sigf(q3 + bh1);   // (j1, r=2s+1)

        *(float4*)(s_hpk + (slice * 128 + jp) * 4) = make_float4(h_a, h_b, h_c, h_d);
        *(float2*)(s_state + (OBSN + j0)     * SQP + 2 * slice) = make_float2(h_a, h_b);
        *(float2*)(s_state + (OBSN + j0 + 1) * SQP + 2 * slice) = make_float2(h_c, h_d);
        ((half2*)s_hT16)[(2 * slice)     * 128 + jp] = __floats2half2_rn(h_a, h_c);
        ((half2*)s_hT16)[(2 * slice + 1) * 128 + jp] = __floats2half2_rn(h_b, h_d);

        if (slice == 1)                            // obs for t+1
            *(float4*)(s_state + ko * SQP + rq * 4) = pf;
        __syncthreads();                           // sync_c

        // ---- output head on slice0 (fp16 operands, f32 accumulate) ----
        if (tid < 128) {
            const uint2* hTa = (const uint2*)(s_hT16 + r_o * HH);
            const uint2* woa = (const uint2*)(s_Wo16 + a_o * WO16P);
            u64 A2 = 0, A3 = 0;
            #pragma unroll 8
            for (int q = 0; q < 64; ++q) {
                uint2 hv = hTa[q], wv = woa[q];
                float2 hA = __half22float2(*(half2*)&hv.x);
                float2 hB = __half22float2(*(half2*)&hv.y);
                float2 wA = __half22float2(*(half2*)&wv.x);
                float2 wB = __half22float2(*(half2*)&wv.y);
                fma2(A2, pack2(hA.x, hA.y), pack2(wA.x, wA.y));
                fma2(A3, pack2(hB.x, hB.y), pack2(wB.x, wB.y));
            }
            float f0, f1, f2, f3;
            unpack2(A2, f0, f1); unpack2(A3, f2, f3);
            float pre_o = bo + ((f0 + f1) + (f2 + f3));
            o_reg = 0.9f * o_reg + 0.1f * sigf(pre_o);
            out[((b0 + r_o) * TT + t) * AA + a_o] = o_reg;
        }
    }

    // ---- final states: [out | h | o] ----
    const long OUT_H = (long)BB * TT * AA;
    const long OUT_O = OUT_H + (long)BB * HH;
    {
        float4 hp = *(float4*)(s_hpk + (slice * 128 + jp) * 4);
        *(float2*)(out + OUT_H + (long)(b0 + 2 * slice)     * HH + j0) = make_float2(hp.x, hp.z);
        *(float2*)(out + OUT_H + (long)(b0 + 2 * slice + 1) * HH + j0) = make_float2(hp.y, hp.w);
    }
    if (tid < 128)
        out[OUT_O + (long)(b0 + r_o) * AA + a_o] = o_reg;
}

extern "C" void kernel_launch(void* const* d_in, const int* in_sizes, int n_in,
                              void* d_out, int out_size) {
    const float* obs   = (const float*)d_in[0];
    const float* W_in  = (const float*)d_in[1];
    const float* W_h   = (const float*)d_in[2];
    const float* b_h   = (const float*)d_in[3];
    const float* W_out = (const float*)d_in[4];
    const float* b_out = (const float*)d_in[5];
    float* out = (float*)d_out;

    prep_kernel<<<(KTOT * HH + 255) / 256, 256>>>(W_in, W_h, W_out);

    size_t shbytes = (size_t)(KTOT * SQP + 4 * 3 * 128 * 4 + 4 * 128 * 4) * sizeof(float)
                   + (size_t)(8 * HH + AA * WO16P + KTOT * HH) * sizeof(__half); // 224,512 B
    cudaFuncSetAttribute(rnn_kernel,
                         cudaFuncAttributeMaxDynamicSharedMemorySize, (int)shbytes);
    rnn_kernel<<<NCTA, NTH, shbytes>>>(obs, b_h, b_out, out);
}

// round 9
// speedup vs baseline: 3.4783x; 3.4783x over previous
#include <cuda_runtime.h>
#include <cuda_fp16.h>

typedef unsigned int u32;

#define TT   512
#define BB   1024
#define OBSN 64
#define HH   256
#define AA   16
#define BM   8
#define NCTA 128
#define NTH  512
#define NKT  20            // k16-tiles over K=320 (obs 0..63 | h 64..319)
#define BKP  328           // B row stride in halfs (stride%32words=4 -> LDSM conflict-free)

__device__ __forceinline__ u32 s2u(const void* p) {
    u32 a;
    asm("{ .reg .u64 t; cvta.to.shared.u64 t, %1; cvt.u32.u64 %0, t; }" : "=r"(a) : "l"(p));
    return a;
}
__device__ __forceinline__ float sigf(float x) {
    return __fdividef(1.0f, 1.0f + __expf(-x));
}
// B fragment load: two 8x8 b16 tiles (k16 x n8) from B[n][k] (col-major of KxN)
__device__ __forceinline__ void ldB(u32& b0, u32& b1, const __half* Bbuf, int kt, int l) {
    const __half* p = Bbuf + (l & 7) * BKP + kt * 16 + ((l & 8) ? 8 : 0);
    asm volatile("ldmatrix.sync.aligned.m8n8.x2.shared.b16 {%0,%1}, [%2];"
                 : "=r"(b0), "=r"(b1) : "r"(s2u(p)));
}
__device__ __forceinline__ void mma16816(float c[4], const u32 a[4], u32 b0, u32 b1) {
    asm volatile(
        "mma.sync.aligned.m16n8k16.row.col.f32.f16.f16.f32 "
        "{%0,%1,%2,%3}, {%4,%5,%6,%7}, {%8,%9}, {%0,%1,%2,%3};"
        : "+f"(c[0]), "+f"(c[1]), "+f"(c[2]), "+f"(c[3])
        : "r"(a[0]), "r"(a[1]), "r"(a[2]), "r"(a[3]), "r"(b0), "r"(b1));
}

__global__ void __launch_bounds__(NTH, 1) rnn_kernel(
    const float* __restrict__ obs,
    const float* __restrict__ W_in,
    const float* __restrict__ W_h,
    const float* __restrict__ b_h,
    const float* __restrict__ W_out,
    const float* __restrict__ b_out,
    float* __restrict__ out)
{
    __shared__ __align__(32) __half s_B[2][8 * BKP];   // (obs_t | h_{t-1}), double-buffered
    __shared__ __align__(32) __half s_A3[AA * HH];     // W_out fp16 [16][256]

    const int tid = threadIdx.x;
    const int w = tid >> 5, l = tid & 31;
    const int grp = l >> 2, tig = l & 3;
    const int b0 = blockIdx.x * BM;
    const int j_a = 16 * w + grp, j_b = j_a + 8;       // owned j rows (M dim)
    const int r0 = 2 * tig, r1 = r0 + 1;               // owned batch cols (N dim)
    const int r_ob = (tid >> 5) & 7, kp = tid & 31;    // obs staging map (tid<256)

    // ---- prologue: A fragments (fused W_in|W_h, fp16) resident in registers ----
    u32 afrag[NKT][4];
    #pragma unroll
    for (int kt = 0; kt < NKT; ++kt) {
        const int k = kt * 16 + 2 * tig;
        #pragma unroll
        for (int half_k = 0; half_k < 2; ++half_k) {   // k and k+8
            const int kk = k + 8 * half_k;
            float xa, ya, xb, yb;
            if (kk < OBSN) {
                xa = W_in[j_a * OBSN + kk]; ya = W_in[j_a * OBSN + kk + 1];
                xb = W_in[j_b * OBSN + kk]; yb = W_in[j_b * OBSN + kk + 1];
            } else {
                xa = W_h[j_a * HH + kk - OBSN]; ya = W_h[j_a * HH + kk - OBSN + 1];
                xb = W_h[j_b * HH + kk - OBSN]; yb = W_h[j_b * HH + kk - OBSN + 1];
            }
            __half2 ha = __floats2half2_rn(xa, ya), hb = __floats2half2_rn(xb, yb);
            afrag[kt][2 * half_k]     = *(u32*)&ha;    // a0/a2: row j_a
            afrag[kt][2 * half_k + 1] = *(u32*)&hb;    // a1/a3: row j_b
        }
    }
    for (int i = tid; i < AA * HH; i += NTH) s_A3[i] = __float2half_rn(W_out[i]);
    for (int i = tid; i < 2 * 8 * BKP; i += NTH) ((__half*)s_B)[i] = __float2half_rn(0.0f);

    const float bha = b_h[j_a], bhb = b_h[j_b];
    const bool hw = (w == 0);                          // head warp
    const float bo_a = hw ? b_out[grp] : 0.0f;
    const float bo_b = hw ? b_out[grp + 8] : 0.0f;
    float hs[4] = {0.f, 0.f, 0.f, 0.f};                // h at (j_a,r0)(j_a,r1)(j_b,r0)(j_b,r1)
    float os[4] = {0.f, 0.f, 0.f, 0.f};
    __syncthreads();                                   // zero-fill visible

    if (tid < 256) {                                   // stage obs_0 into buffer 0
        float2 ov = *(const float2*)(obs + ((long)(b0 + r_ob) * TT + 0) * OBSN + 2 * kp);
        *(__half2*)(&s_B[0][r_ob * BKP + 2 * kp]) = __floats2half2_rn(ov.x, ov.y);
    }
    __syncthreads();

    const long OUT_H = (long)BB * TT * AA;
    const long OUT_O = OUT_H + (long)BB * HH;
    int cur = 0;

    for (int t = 0; t <= TT; ++t) {
        float2 opf;
        if (tid < 256 && t < TT) {                     // prefetch obs_{t+1}
            int tn = (t + 1 < TT) ? t + 1 : TT - 1;
            opf = *(const float2*)(obs + ((long)(b0 + r_ob) * TT + tn) * OBSN + 2 * kp);
        }
        const __half* Bc = s_B[cur];

        // ---- main MMA: pre_h = b_h + [obs_t|h_{t-1}] . [W_in|W_h]^T ----
        float c[4];
        if (t < TT) {
            c[0] = bha; c[1] = bha; c[2] = bhb; c[3] = bhb;
            #pragma unroll
            for (int kt = 0; kt < NKT; ++kt) {
                u32 bf0, bf1; ldB(bf0, bf1, Bc, kt, l);
                mma16816(c, afrag[kt], bf0, bf1);
            }
        }
        // ---- head MMA on warp 0: h_{t-1} . W_out^T  (k-tiles 4..19 only) ----
        if (hw) {
            float c3[4] = {0.f, 0.f, 0.f, 0.f};
            #pragma unroll
            for (int kt = 4; kt < NKT; ++kt) {
                const int k = (kt - 4) * 16 + 2 * tig;
                u32 a3[4];
                a3[0] = *(const u32*)(s_A3 + grp * HH + k);
                a3[1] = *(const u32*)(s_A3 + (grp + 8) * HH + k);
                a3[2] = *(const u32*)(s_A3 + grp * HH + k + 8);
                a3[3] = *(const u32*)(s_A3 + (grp + 8) * HH + k + 8);
                u32 bf0, bf1; ldB(bf0, bf1, Bc, kt, l);
                mma16816(c3, a3, bf0, bf1);
            }
            if (t >= 1) {                              // emit o_{t-1}
                os[0] = 0.9f * os[0] + 0.1f * sigf(c3[0] + bo_a);
                os[1] = 0.9f * os[1] + 0.1f * sigf(c3[1] + bo_a);
                os[2] = 0.9f * os[2] + 0.1f * sigf(c3[2] + bo_b);
                os[3] = 0.9f * os[3] + 0.1f * sigf(c3[3] + bo_b);
                out[((long)(b0 + r0) * TT + (t - 1)) * AA + grp]     = os[0];
                out[((long)(b0 + r1) * TT + (t - 1)) * AA + grp]     = os[1];
                out[((long)(b0 + r0) * TT + (t - 1)) * AA + grp + 8] = os[2];
                out[((long)(b0 + r1) * TT + (t - 1)) * AA + grp + 8] = os[3];
            }
        }
        if (t == TT) break;

        // ---- h blend in registers, publish h_t + obs_{t+1} to next buffer ----
        hs[0] = 0.9f * hs[0] + 0.1f * sigf(c[0]);
        hs[1] = 0.9f * hs[1] + 0.1f * sigf(c[1]);
        hs[2] = 0.9f * hs[2] + 0.1f * sigf(c[2]);
        hs[3] = 0.9f * hs[3] + 0.1f * sigf(c[3]);

        __half* Bn = (__half*)s_B[cur ^ 1];
        Bn[r0 * BKP + OBSN + j_a] = __float2half_rn(hs[0]);
        Bn[r1 * BKP + OBSN + j_a] = __float2half_rn(hs[1]);
        Bn[r0 * BKP + OBSN + j_b] = __float2half_rn(hs[2]);
        Bn[r1 * BKP + OBSN + j_b] = __float2half_rn(hs[3]);
        if (tid < 256)
            *(__half2*)(&Bn[r_ob * BKP + 2 * kp]) = __floats2half2_rn(opf.x, opf.y);
        __syncthreads();
        cur ^= 1;
    }

    // ---- final states: [out | h | o] ----
    out[OUT_H + (long)(b0 + r0) * HH + j_a] = hs[0];
    out[OUT_H + (long)(b0 + r1) * HH + j_a] = hs[1];
    out[OUT_H + (long)(b0 + r0) * HH + j_b] = hs[2];
    out[OUT_H + (long)(b0 + r1) * HH + j_b] = hs[3];
    if (hw) {
        out[OUT_O + (long)(b0 + r0) * AA + grp]     = os[0];
        out[OUT_O + (long)(b0 + r1) * AA + grp]     = os[1];
        out[OUT_O + (long)(b0 + r0) * AA + grp + 8] = os[2];
        out[OUT_O + (long)(b0 + r1) * AA + grp + 8] = os[3];
    }
}

extern "C" void kernel_launch(void* const* d_in, const int* in_sizes, int n_in,
                              void* d_out, int out_size) {
    const float* obs   = (const float*)d_in[0];
    const float* W_in  = (const float*)d_in[1];
    const float* W_h   = (const float*)d_in[2];
    const float* b_h   = (const float*)d_in[3];
    const float* W_out = (const float*)d_in[4];
    const float* b_out = (const float*)d_in[5];
    float* out = (float*)d_out;

    rnn_kernel<<<NCTA, NTH>>>(obs, W_in, W_h, b_h, W_out, b_out, out);
}

// round 10
// speedup vs baseline: 4.8483x; 1.3939x over previous
#include <cuda_runtime.h>
#include <cuda_fp16.h>

typedef unsigned int u32;

#define TT    512
#define BB    1024
#define OBSN  64
#define HH    256
#define AA    16
#define BM    8
#define NCTA  128
#define NTH   512
#define NKT   20           // k16-tiles over K=320 (obs 0..63 | h 64..319)
#define NPAIR 10           // ldmatrix.x4 pairs
#define BKP   328          // B row stride in halfs (164 words % 32 = 4 -> conflict-free LDSM)

__device__ __forceinline__ u32 s2u(const void* p) {
    u32 a;
    asm("{ .reg .u64 t; cvta.to.shared.u64 t, %1; cvt.u32.u64 %0, t; }" : "=r"(a) : "l"(p));
    return a;
}
__device__ __forceinline__ float sigf(float x) {
    return __fdividef(1.0f, 1.0f + __expf(-x));
}
// load B frags for tile pair p (tiles 2p, 2p+1): {x,y}=tile 2p, {z,w}=tile 2p+1
__device__ __forceinline__ uint4 ldB4(const __half* Bbuf, int p, int l) {
    uint4 r;
    const __half* ptr = Bbuf + (l & 7) * BKP + p * 32 + 8 * (l >> 3);
    asm volatile("ldmatrix.sync.aligned.m8n8.x4.shared.b16 {%0,%1,%2,%3}, [%4];"
                 : "=r"(r.x), "=r"(r.y), "=r"(r.z), "=r"(r.w) : "r"(s2u(ptr)));
    return r;
}
__device__ __forceinline__ void mma16816(float c[4], const u32 a[4], u32 b0, u32 b1) {
    asm volatile(
        "mma.sync.aligned.m16n8k16.row.col.f32.f16.f16.f32 "
        "{%0,%1,%2,%3}, {%4,%5,%6,%7}, {%8,%9}, {%0,%1,%2,%3};"
        : "+f"(c[0]), "+f"(c[1]), "+f"(c[2]), "+f"(c[3])
        : "r"(a[0]), "r"(a[1]), "r"(a[2]), "r"(a[3]), "r"(b0), "r"(b1));
}

__global__ void __launch_bounds__(NTH, 1) rnn_kernel(
    const float* __restrict__ obs,
    const float* __restrict__ W_in,
    const float* __restrict__ W_h,
    const float* __restrict__ b_h,
    const float* __restrict__ W_out,
    const float* __restrict__ b_out,
    float* __restrict__ out)
{
    __shared__ __align__(32) __half s_B[2][8 * BKP];   // (obs_t | h_{t-1}), double-buffered
    __shared__ uint4  s_A3f[16][32];                   // W_out A-frags, per (h-tile, lane)
    __shared__ float4 s_hp[2][4][32];                  // head partials, double-buffered

    const int tid = threadIdx.x;
    const int w = tid >> 5, l = tid & 31;
    const int grp = l >> 2, tig = l & 3;
    const int b0 = blockIdx.x * BM;
    const int j_a = 16 * w + grp, j_b = j_a + 8;       // owned j rows
    const int r0 = 2 * tig, r1 = r0 + 1;               // owned batch cols
    const bool ow = (tid >= 256);                      // obs-staging warps (8-15)
    const int r_ob = (tid >> 5) & 7, kp = l;           // obs map for those warps

    // ---- prologue: main A fragments resident in registers ----
    u32 afrag[NKT][4];
    #pragma unroll
    for (int kt = 0; kt < NKT; ++kt) {
        const int k = kt * 16 + 2 * tig;
        #pragma unroll
        for (int hk = 0; hk < 2; ++hk) {
            const int kk = k + 8 * hk;
            float xa, ya, xb, yb;
            if (kk < OBSN) {
                xa = W_in[j_a * OBSN + kk]; ya = W_in[j_a * OBSN + kk + 1];
                xb = W_in[j_b * OBSN + kk]; yb = W_in[j_b * OBSN + kk + 1];
            } else {
                xa = W_h[j_a * HH + kk - OBSN]; ya = W_h[j_a * HH + kk - OBSN + 1];
                xb = W_h[j_b * HH + kk - OBSN]; yb = W_h[j_b * HH + kk - OBSN + 1];
            }
            __half2 ha = __floats2half2_rn(xa, ya), hb = __floats2half2_rn(xb, yb);
            afrag[kt][2 * hk]     = *(u32*)&ha;
            afrag[kt][2 * hk + 1] = *(u32*)&hb;
        }
    }
    // W_out A-frags pre-packed for LDS.128 (h-tile ht: k_h = ht*16)
    {
        int i = tid;                                   // 512 items, one per thread
        int tile = i >> 5, ln = i & 31;
        int g = ln >> 2, tg = ln & 3;
        int kh = tile * 16 + 2 * tg;
        __half2 a0 = __floats2half2_rn(W_out[g * HH + kh],       W_out[g * HH + kh + 1]);
        __half2 a1 = __floats2half2_rn(W_out[(g + 8) * HH + kh], W_out[(g + 8) * HH + kh + 1]);
        __half2 a2 = __floats2half2_rn(W_out[g * HH + kh + 8],   W_out[g * HH + kh + 9]);
        __half2 a3 = __floats2half2_rn(W_out[(g + 8) * HH + kh + 8], W_out[(g + 8) * HH + kh + 9]);
        s_A3f[tile][ln] = make_uint4(*(u32*)&a0, *(u32*)&a1, *(u32*)&a2, *(u32*)&a3);
    }
    for (int i = tid; i < 2 * 8 * BKP; i += NTH) ((__half*)s_B)[i] = __float2half_rn(0.0f);

    const float bha = b_h[j_a], bhb = b_h[j_b];
    const float bo_a = (w == 0) ? b_out[grp] : 0.0f;
    const float bo_b = (w == 0) ? b_out[grp + 8] : 0.0f;
    float hs[4] = {0.f, 0.f, 0.f, 0.f};
    float os[4] = {0.f, 0.f, 0.f, 0.f};
    __syncthreads();

    if (ow) {                                          // stage obs_0 into buffer 0
        float2 ov = *(const float2*)(obs + ((long)(b0 + r_ob) * TT + 0) * OBSN + 2 * kp);
        *(__half2*)(&s_B[0][r_ob * BKP + 2 * kp]) = __floats2half2_rn(ov.x, ov.y);
    }
    __syncthreads();

    const long OUT_H = (long)BB * TT * AA;
    const long OUT_O = OUT_H + (long)BB * HH;
    int cur = 0;

    for (int t = 0; t <= TT + 1; ++t) {
        float2 opf;
        if (ow && t < TT) {                            // prefetch obs_{t+1}
            int tn = (t + 1 < TT) ? t + 1 : TT - 1;
            opf = *(const float2*)(obs + ((long)(b0 + r_ob) * TT + tn) * OBSN + 2 * kp);
        }
        const __half* Bc = s_B[cur];

        // ---- main MMA: 4 independent accumulator chains, pipelined x4 LDSM ----
        float c0[4], c1[4], c2[4], c3[4];
        if (t < TT) {
            c0[0] = bha; c0[1] = bha; c0[2] = bhb; c0[3] = bhb;
            #pragma unroll
            for (int i = 0; i < 4; ++i) { c1[i] = 0.f; c2[i] = 0.f; c3[i] = 0.f; }
            uint4 ba = ldB4(Bc, 0, l), bb = ldB4(Bc, 1, l);
            #pragma unroll
            for (int p = 0; p < NPAIR; p += 2) {       // tiles 2p..2p+3 -> chains 0..3
                uint4 bc, bd;
                if (p + 2 < NPAIR) bc = ldB4(Bc, p + 2, l);
                if (p + 3 < NPAIR) bd = ldB4(Bc, p + 3, l);
                mma16816(c0, afrag[2 * p],     ba.x, ba.y);
                mma16816(c1, afrag[2 * p + 1], ba.z, ba.w);
                mma16816(c2, afrag[2 * p + 2], bb.x, bb.y);
                mma16816(c3, afrag[2 * p + 3], bb.z, bb.w);
                ba = bc; bb = bd;
            }
        }

        // ---- head partials on warps 0-3 (h_{t-1}.W_out^T, 4 k-tiles each) ----
        if (w < 4 && t >= 1 && t <= TT) {
            uint4 hb0 = ldB4(Bc, 2 + 2 * w, l), hb1 = ldB4(Bc, 3 + 2 * w, l);
            uint4 A0 = s_A3f[4 * w + 0][l], A1 = s_A3f[4 * w + 1][l];
            uint4 A2 = s_A3f[4 * w + 2][l], A3 = s_A3f[4 * w + 3][l];
            float cp[4] = {0.f, 0.f, 0.f, 0.f};
            mma16816(cp, (const u32*)&A0, hb0.x, hb0.y);
            mma16816(cp, (const u32*)&A1, hb0.z, hb0.w);
            mma16816(cp, (const u32*)&A2, hb1.x, hb1.y);
            mma16816(cp, (const u32*)&A3, hb1.z, hb1.w);
            s_hp[t & 1][w][l] = make_float4(cp[0], cp[1], cp[2], cp[3]);
        }

        // ---- warp 0: combine partials from step t-1, emit o_{t-2} ----
        if (w == 0 && t >= 2) {
            float4 q0 = s_hp[(t & 1) ^ 1][0][l], q1 = s_hp[(t & 1) ^ 1][1][l];
            float4 q2 = s_hp[(t & 1) ^ 1][2][l], q3 = s_hp[(t & 1) ^ 1][3][l];
            float p0 = q0.x + q1.x + q2.x + q3.x + bo_a;
            float p1 = q0.y + q1.y + q2.y + q3.y + bo_a;
            float p2 = q0.z + q1.z + q2.z + q3.z + bo_b;
            float p3 = q0.w + q1.w + q2.w + q3.w + bo_b;
            os[0] = 0.9f * os[0] + 0.1f * sigf(p0);
            os[1] = 0.9f * os[1] + 0.1f * sigf(p1);
            os[2] = 0.9f * os[2] + 0.1f * sigf(p2);
            os[3] = 0.9f * os[3] + 0.1f * sigf(p3);
            const int te = t - 2;
            out[((long)(b0 + r0) * TT + te) * AA + grp]     = os[0];
            out[((long)(b0 + r1) * TT + te) * AA + grp]     = os[1];
            out[((long)(b0 + r0) * TT + te) * AA + grp + 8] = os[2];
            out[((long)(b0 + r1) * TT + te) * AA + grp + 8] = os[3];
        }

        // ---- blend h in registers, publish h_t + obs_{t+1} ----
        if (t < TT) {
            float f0 = (c0[0] + c1[0]) + (c2[0] + c3[0]);
            float f1 = (c0[1] + c1[1]) + (c2[1] + c3[1]);
            float f2 = (c0[2] + c1[2]) + (c2[2] + c3[2]);
            float f3 = (c0[3] + c1[3]) + (c2[3] + c3[3]);
            hs[0] = 0.9f * hs[0] + 0.1f * sigf(f0);
            hs[1] = 0.9f * hs[1] + 0.1f * sigf(f1);
            hs[2] = 0.9f * hs[2] + 0.1f * sigf(f2);
            hs[3] = 0.9f * hs[3] + 0.1f * sigf(f3);
            __half* Bn = (__half*)s_B[cur ^ 1];
            Bn[r0 * BKP + OBSN + j_a] = __float2half_rn(hs[0]);
            Bn[r1 * BKP + OBSN + j_a] = __float2half_rn(hs[1]);
            Bn[r0 * BKP + OBSN + j_b] = __float2half_rn(hs[2]);
            Bn[r1 * BKP + OBSN + j_b] = __float2half_rn(hs[3]);
            if (ow)
                *(__half2*)(&Bn[r_ob * BKP + 2 * kp]) = __floats2half2_rn(opf.x, opf.y);
        }
        if (t <= TT) __syncthreads();
        if (t < TT) cur ^= 1;
    }

    // ---- final states: [out | h | o] ----
    out[OUT_H + (long)(b0 + r0) * HH + j_a] = hs[0];
    out[OUT_H + (long)(b0 + r1) * HH + j_a] = hs[1];
    out[OUT_H + (long)(b0 + r0) * HH + j_b] = hs[2];
    out[OUT_H + (long)(b0 + r1) * HH + j_b] = hs[3];
    if (w == 0) {
        out[OUT_O + (long)(b0 + r0) * AA + grp]     = os[0];
        out[OUT_O + (long)(b0 + r1) * AA + grp]     = os[1];
        out[OUT_O + (long)(b0 + r0) * AA + grp + 8] = os[2];
        out[OUT_O + (long)(b0 + r1) * AA + grp + 8] = os[3];
    }
}

extern "C" void kernel_launch(void* const* d_in, const int* in_sizes, int n_in,
                              void* d_out, int out_size) {
    const float* obs   = (const float*)d_in[0];
    const float* W_in  = (const float*)d_in[1];
    const float* W_h   = (const float*)d_in[2];
    const float* b_h   = (const float*)d_in[3];
    const float* W_out = (const float*)d_in[4];
    const float* b_out = (const float*)d_in[5];
    float* out = (float*)d_out;

    rnn_kernel<<<NCTA, NTH>>>(obs, W_in, W_h, b_h, W_out, b_out, out);
}

// round 12
// speedup vs baseline: 5.1856x; 1.0696x over previous
#include <cuda_runtime.h>
#include <cuda_fp16.h>

typedef unsigned int u32;

#define TT   512
#define BB   1024
#define OBSN 64
#define HH   256
#define AA   16
#define BM   8
#define NCTA 128
#define NTH  512
#define BKP  328          // B row stride in halfs (conflict-free LDSM)
#define HPR  144          // s_hp row stride in floats (e = a*9+r, 9 coprime w/ 32)

__device__ __forceinline__ u32 s2u(const void* p) {
    u32 a;
    asm("{ .reg .u64 t; cvta.to.shared.u64 t, %1; cvt.u32.u64 %0, t; }" : "=r"(a) : "l"(p));
    return a;
}
// sigmoid(x) = 0.5 + 0.5*tanh(x/2)  (MUFU.TANH: 1 MUFU vs exp+rcp's 2)
__device__ __forceinline__ float sigt(float x) {
    float t;
    asm("tanh.approx.f32 %0, %1;" : "=f"(t) : "f"(0.5f * x));
    return fmaf(0.5f, t, 0.5f);
}
__device__ __forceinline__ uint4 ldB4(const __half* base) {
    uint4 r;
    asm volatile("ldmatrix.sync.aligned.m8n8.x4.shared.b16 {%0,%1,%2,%3}, [%4];"
                 : "=r"(r.x), "=r"(r.y), "=r"(r.z), "=r"(r.w) : "r"(s2u(base)));
    return r;
}
__device__ __forceinline__ uint2 ldB2(const __half* base) {
    uint2 r;
    asm volatile("ldmatrix.sync.aligned.m8n8.x2.shared.b16 {%0,%1}, [%2];"
                 : "=r"(r.x), "=r"(r.y) : "r"(s2u(base)));
    return r;
}
__device__ __forceinline__ void mma16816(float c[4], const u32* a, u32 b0, u32 b1) {
    asm volatile(
        "mma.sync.aligned.m16n8k16.row.col.f32.f16.f16.f32 "
        "{%0,%1,%2,%3}, {%4,%5,%6,%7}, {%8,%9}, {%0,%1,%2,%3};"
        : "+f"(c[0]), "+f"(c[1]), "+f"(c[2]), "+f"(c[3])
        : "r"(a[0]), "r"(a[1]), "r"(a[2]), "r"(a[3]), "r"(b0), "r"(b1));
}

__global__ void __launch_bounds__(NTH, 1) rnn_kernel(
    const float* __restrict__ obs,
    const float* __restrict__ W_in,
    const float* __restrict__ W_h,
    const float* __restrict__ b_h,
    const float* __restrict__ W_out,
    const float* __restrict__ b_out,
    float* __restrict__ out)
{
    __shared__ __align__(32) __half s_B[2][8 * BKP];   // (obs_t | h_{t-1}), double-buffered
    __shared__ float s_mp[8][8][32];                   // K-half1 partials: [frag f][m][lane]
    __shared__ float s_hp[2][16][HPR];                 // head partials, double-buffered

    const int tid = threadIdx.x;
    const int w = tid >> 5, l = tid & 31;
    const int kh = w >> 3, m = w & 7;                  // K-half, M-group (M=32 rows)
    const int grp = l >> 2, tig = l & 3;
    const int b0 = blockIdx.x * BM;
    const int jA = 32 * m + grp;                       // tile0 rows jA, jA+8
    const int jB = jA + 16;                            // tile1 rows jB, jB+8
    const int r0 = 2 * tig, r1 = r0 + 1;

    // ---- prologue: A fragments for this warp's K-half (10 k-tiles x 2 M-tiles) ----
    u32 afrag[10][8];
    #pragma unroll
    for (int kt = 0; kt < 10; ++kt) {
        const int ktg = 10 * kh + kt;
        #pragma unroll
        for (int tile = 0; tile < 2; ++tile) {
            const int ja = jA + 16 * tile, jb = ja + 8;
            #pragma unroll
            for (int hk = 0; hk < 2; ++hk) {
                const int kk = ktg * 16 + 2 * tig + 8 * hk;
                float xa, ya, xb, yb;
                if (kk < OBSN) {
                    xa = W_in[ja * OBSN + kk]; ya = W_in[ja * OBSN + kk + 1];
                    xb = W_in[jb * OBSN + kk]; yb = W_in[jb * OBSN + kk + 1];
                } else {
                    xa = W_h[ja * HH + kk - OBSN]; ya = W_h[ja * HH + kk - OBSN + 1];
                    xb = W_h[jb * HH + kk - OBSN]; yb = W_h[jb * HH + kk - OBSN + 1];
                }
                __half2 ha = __floats2half2_rn(xa, ya), hb = __floats2half2_rn(xb, yb);
                afrag[kt][tile * 4 + 2 * hk]     = *(u32*)&ha;
                afrag[kt][tile * 4 + 2 * hk + 1] = *(u32*)&hb;
            }
        }
    }
    // head A-frag: warp w owns head k-tile (h cols 16w..16w+16), loop-invariant
    u32 a3[4];
    {
        const int khd = 16 * w + 2 * tig;
        __half2 h0 = __floats2half2_rn(W_out[grp * HH + khd],           W_out[grp * HH + khd + 1]);
        __half2 h1 = __floats2half2_rn(W_out[(grp + 8) * HH + khd],     W_out[(grp + 8) * HH + khd + 1]);
        __half2 h2 = __floats2half2_rn(W_out[grp * HH + khd + 8],       W_out[grp * HH + khd + 9]);
        __half2 h3 = __floats2half2_rn(W_out[(grp + 8) * HH + khd + 8], W_out[(grp + 8) * HH + khd + 9]);
        a3[0] = *(u32*)&h0; a3[1] = *(u32*)&h1; a3[2] = *(u32*)&h2; a3[3] = *(u32*)&h3;
    }
    // biases (used by K-half0, which finalizes)
    const float bA0 = b_h[jA], bA1 = b_h[jA + 8], bB0 = b_h[jB], bB1 = b_h[jB + 8];

    // combiner mapping: threads 256..383 own one (a, r) output element each
    const int cq = tid - 256;                          // valid for warps 8-11
    const int ca = cq & 15, cr = (cq >> 4) & 7;
    const bool comb = (tid >= 256 && tid < 384);
    const float bo = comb ? b_out[ca] : 0.0f;
    float o_reg = 0.0f;
    float hs[8];
    #pragma unroll
    for (int i = 0; i < 8; ++i) hs[i] = 0.0f;

    for (int i = tid; i < 2 * 8 * BKP / 2; i += NTH) ((u32*)s_B)[i] = 0u;
    __syncthreads();

    // stage obs_0 (K-half1 threads: 256 lanes <-> [8 rows][32 col-pairs])
    const int row_ob = (tid >> 5) & 7, cp_ob = l;
    if (kh == 1) {
        float2 ov = *(const float2*)(obs + ((long)(b0 + row_ob) * TT + 0) * OBSN + 2 * cp_ob);
        *(__half2*)(&s_B[0][row_ob * BKP + 2 * cp_ob]) = __floats2half2_rn(ov.x, ov.y);
    }
    __syncthreads();

    const long OUT_H = (long)BB * TT * AA;
    const long OUT_O = OUT_H + (long)BB * HH;
    int cur = 0;

    for (int t = 0; t <= TT + 1; ++t) {
        const __half* Bc = s_B[cur];
        float2 opf;
        if (kh == 1 && t < TT) {                       // prefetch obs_{t+1}
            int tn = (t + 1 < TT) ? t + 1 : TT - 1;
            opf = *(const float2*)(obs + ((long)(b0 + row_ob) * TT + tn) * OBSN + 2 * cp_ob);
        }

        // ---- combiner: finish head of step t-1 -> emit o_{t-2} ----
        if (comb && t >= 2) {
            const int pb = (t - 1) & 1;
            float s = bo;
            #pragma unroll
            for (int w2 = 0; w2 < 16; ++w2) s += s_hp[pb][w2][ca * 9 + cr];
            o_reg = 0.9f * o_reg + 0.1f * sigt(s);
            out[((long)(b0 + cr) * TT + (t - 2)) * AA + ca] = o_reg;
        }

        // ---- main MMA over own K-half: 4 chains (2 M-tiles x k-parity), depth 5 ----
        float c0[4], c1[4], c2[4], c3[4];
        float f0[4], f1[4];
        if (t < TT) {
            if (kh == 0) {
                c0[0] = bA0; c0[1] = bA0; c0[2] = bA1; c0[3] = bA1;
                c2[0] = bB0; c2[1] = bB0; c2[2] = bB1; c2[3] = bB1;
            } else {
                #pragma unroll
                for (int i = 0; i < 4; ++i) { c0[i] = 0.f; c2[i] = 0.f; }
            }
            #pragma unroll
            for (int i = 0; i < 4; ++i) { c1[i] = 0.f; c3[i] = 0.f; }

            const __half* Bb = Bc + (l & 7) * BKP + kh * 160 + 8 * (l >> 3);
            uint4 ba = ldB4(Bb), bn;
            #pragma unroll
            for (int p = 0; p < 5; ++p) {              // pair p = k-tiles 2p, 2p+1
                if (p < 4) bn = ldB4(Bb + (p + 1) * 32);
                mma16816(c0, &afrag[2 * p][0],     ba.x, ba.y);   // tile0, even kt
                mma16816(c2, &afrag[2 * p][4],     ba.x, ba.y);   // tile1, even kt
                mma16816(c1, &afrag[2 * p + 1][0], ba.z, ba.w);   // tile0, odd kt
                mma16816(c3, &afrag[2 * p + 1][4], ba.z, ba.w);   // tile1, odd kt
                ba = bn;
            }
            #pragma unroll
            for (int i = 0; i < 4; ++i) { f0[i] = c0[i] + c1[i]; f1[i] = c2[i] + c3[i]; }
            if (kh == 1) {                             // publish K-half1 partials
                #pragma unroll
                for (int i = 0; i < 4; ++i) {
                    s_mp[i][m][l]     = f0[i];
                    s_mp[4 + i][m][l] = f1[i];
                }
            }
        }

        // ---- head: one k-tile per warp (reads h part of Bc) ----
        if (t >= 1 && t <= TT) {
            const __half* Hb = Bc + (l & 7) * BKP + OBSN + 16 * w + 8 * ((l >> 3) & 1);
            uint2 hb = ldB2(Hb);
            float cp[4] = {0.f, 0.f, 0.f, 0.f};
            mma16816(cp, a3, hb.x, hb.y);
            float* hp = s_hp[t & 1][w];
            hp[grp * 9 + r0]       = cp[0];
            hp[grp * 9 + r1]       = cp[1];
            hp[(grp + 8) * 9 + r0] = cp[2];
            hp[(grp + 8) * 9 + r1] = cp[3];
        }
        __syncthreads();                               // bar1: partial handoff

        if (t < TT) {
            __half* Bn = (__half*)s_B[cur ^ 1];
            if (kh == 0) {
                // combine K-halves, sigmoid, blend, publish h_t
                #pragma unroll
                for (int i = 0; i < 4; ++i) {
                    f0[i] += s_mp[i][m][l];
                    f1[i] += s_mp[4 + i][m][l];
                }
                hs[0] = 0.9f * hs[0] + 0.1f * sigt(f0[0]);
                hs[1] = 0.9f * hs[1] + 0.1f * sigt(f0[1]);
                hs[2] = 0.9f * hs[2] + 0.1f * sigt(f0[2]);
                hs[3] = 0.9f * hs[3] + 0.1f * sigt(f0[3]);
                hs[4] = 0.9f * hs[4] + 0.1f * sigt(f1[0]);
                hs[5] = 0.9f * hs[5] + 0.1f * sigt(f1[1]);
                hs[6] = 0.9f * hs[6] + 0.1f * sigt(f1[2]);
                hs[7] = 0.9f * hs[7] + 0.1f * sigt(f1[3]);
                Bn[r0 * BKP + OBSN + jA]     = __float2half_rn(hs[0]);
                Bn[r1 * BKP + OBSN + jA]     = __float2half_rn(hs[1]);
                Bn[r0 * BKP + OBSN + jA + 8] = __float2half_rn(hs[2]);
                Bn[r1 * BKP + OBSN + jA + 8] = __float2half_rn(hs[3]);
                Bn[r0 * BKP + OBSN + jB]     = __float2half_rn(hs[4]);
                Bn[r1 * BKP + OBSN + jB]     = __float2half_rn(hs[5]);
                Bn[r0 * BKP + OBSN + jB + 8] = __float2half_rn(hs[6]);
                Bn[r1 * BKP + OBSN + jB + 8] = __float2half_rn(hs[7]);
            } else {                                   // stage obs_{t+1}
                *(__half2*)(&Bn[row_ob * BKP + 2 * cp_ob]) = __floats2half2_rn(opf.x, opf.y);
            }
        }
        __syncthreads();                               // bar2: B_next + s_mp reuse
        if (t < TT) cur ^= 1;
    }

    // ---- final states: [out | h | o] ----
    if (kh == 0) {
        out[OUT_H + (long)(b0 + r0) * HH + jA]     = hs[0];
        out[OUT_H + (long)(b0 + r1) * HH + jA]     = hs[1];
        out[OUT_H + (long)(b0 + r0) * HH + jA + 8] = hs[2];
        out[OUT_H + (long)(b0 + r1) * HH + jA + 8] = hs[3];
        out[OUT_H + (long)(b0 + r0) * HH + jB]     = hs[4];
        out[OUT_H + (long)(b0 + r1) * HH + jB]     = hs[5];
        out[OUT_H + (long)(b0 + r0) * HH + jB + 8] = hs[6];
        out[OUT_H + (long)(b0 + r1) * HH + jB + 8] = hs[7];
    }
    if (comb)
        out[OUT_O + (long)(b0 + cr) * AA + ca] = o_reg;
}

extern "C" void kernel_launch(void* const* d_in, const int* in_sizes, int n_in,
                              void* d_out, int out_size) {
    const float* obs   = (const float*)d_in[0];
    const float* W_in  = (const float*)d_in[1];
    const float* W_h   = (const float*)d_in[2];
    const float* b_h   = (const float*)d_in[3];
    const float* W_out = (const float*)d_in[4];
    const float* b_out = (const float*)d_in[5];
    float* out = (float*)d_out;

    rnn_kernel<<<NCTA, NTH>>>(obs, W_in, W_h, b_h, W_out, b_out, out);
}